// round 1
// baseline (speedup 1.0000x reference)
#include <cuda_runtime.h>
#include <cuda_bf16.h>
#include <cstdint>

// Problem constants
#define Bn 8
#define Nn 16384
#define Cc 4
#define Gg 128          // NUM_GROUPS
#define GS 32           // GROUP_SIZE
#define UK 128          // UPSCALE_K
#define FPS_T 1024
#define PPT (Nn / FPS_T)   // 16 points per thread
#define GQ_T 256
#define CHUNK (Nn / GQ_T)  // 64 points per thread

// Exact f32 constants matching JAX (python doubles rounded to f32)
__device__ __forceinline__ float NEG_INF() { return __int_as_float(0xff800000); }
__device__ __forceinline__ float POS_INF() { return __int_as_float(0x7f800000); }
#define RADIUS_F 0.1f
#define R2_F 0.01f                  // f32(0.01) — NOT 0.1f*0.1f
#define THR_F 0.0036f               // f32((2*0.1*0.3)^2)

// Output layout: groups | centers | mask
#define OUT_GROUPS 0
#define OUT_CENTERS (Bn * Gg * GS * Cc)          // 131072
#define OUT_MASK (OUT_CENTERS + Bn * Gg * 3)     // 134144

// Scratch (no allocations allowed)
__device__ float g_centers[Bn * Gg * 3];
__device__ int   g_retain[Bn * Gg];
__device__ int   g_glen[Bn];

// (value, index) max-reduction with min-index tie-break (matches jnp.argmax / lax.top_k)
__device__ __forceinline__ void argmax_red(float& v, int& i) {
    #pragma unroll
    for (int off = 16; off > 0; off >>= 1) {
        float ov = __shfl_down_sync(0xffffffffu, v, off);
        int   oi = __shfl_down_sync(0xffffffffu, i, off);
        if (ov > v || (ov == v && oi < i)) { v = ov; i = oi; }
    }
}

// ---------------------------------------------------------------------------
// Kernel 1: FPS (one block per batch) + fused cluster-NMS + centers output
// ---------------------------------------------------------------------------
__global__ __launch_bounds__(FPS_T) void fps_kernel(const float4* __restrict__ pts,
                                                    const int* __restrict__ lengths,
                                                    float* __restrict__ out) {
    const int b = blockIdx.x;
    const float4* __restrict__ p = pts + (size_t)b * Nn;
    const int len = lengths[b];
    const int t = threadIdx.x;
    const int lane = t & 31, warp = t >> 5;

    if (t == 0) g_glen[b] = 0;

    float px[PPT], py[PPT], pz[PPT], mind[PPT];
    #pragma unroll
    for (int k = 0; k < PPT; k++) {
        const int i = t + k * FPS_T;
        float4 v = p[i];
        px[k] = v.x; py[k] = v.y; pz[k] = v.z;
        mind[k] = (i < len) ? POS_INF() : NEG_INF();
    }

    __shared__ float s_cx, s_cy, s_cz;
    __shared__ float s_centers[Gg * 3];
    __shared__ float s_wv[32];
    __shared__ int s_wi[32];
    __shared__ int s_best;

    int cur = 0;
    for (int s = 0; s < Gg; s++) {
        if (t == 0) {
            float4 v = p[cur];
            s_cx = v.x; s_cy = v.y; s_cz = v.z;
            s_centers[s * 3 + 0] = v.x;
            s_centers[s * 3 + 1] = v.y;
            s_centers[s * 3 + 2] = v.z;
        }
        __syncthreads();
        if (s == Gg - 1) break;

        const float cx = s_cx, cy = s_cy, cz = s_cz;
        float bv = NEG_INF();
        int bi = 0x7fffffff;
        #pragma unroll
        for (int k = 0; k < PPT; k++) {
            float dx = px[k] - cx, dy = py[k] - cy, dz = pz[k] - cz;
            float d = dx * dx + dy * dy + dz * dz;
            float m = fminf(mind[k], d);
            mind[k] = m;
            const int i = t + k * FPS_T;
            if (m > bv || (m == bv && i < bi)) { bv = m; bi = i; }
        }
        argmax_red(bv, bi);
        if (lane == 0) { s_wv[warp] = bv; s_wi[warp] = bi; }
        __syncthreads();
        if (warp == 0) {
            bv = s_wv[lane]; bi = s_wi[lane];
            argmax_red(bv, bi);
            if (lane == 0) s_best = bi;
        }
        __syncthreads();
        cur = s_best;
    }

    // Write centers (shared is consistent: last record was followed by __syncthreads)
    for (int i = t; i < Gg * 3; i += FPS_T) {
        float v = s_centers[i];
        g_centers[(size_t)b * Gg * 3 + i] = v;
        out[OUT_CENTERS + (size_t)b * Gg * 3 + i] = v;
    }

    // Greedy cluster-NMS in FPS order (warp 0; each lane owns centers lane+q*32)
    if (warp == 0) {
        float kx[4], ky[4], kz[4];
        bool kp[4];
        #pragma unroll
        for (int q = 0; q < 4; q++) {
            const int i = lane + q * 32;
            kx[q] = s_centers[i * 3 + 0];
            ky[q] = s_centers[i * 3 + 1];
            kz[q] = s_centers[i * 3 + 2];
            kp[q] = false;
        }
        for (int j = 0; j < Gg; j++) {
            const float jx = s_centers[j * 3 + 0];
            const float jy = s_centers[j * 3 + 1];
            const float jz = s_centers[j * 3 + 2];
            bool conflict = false;
            #pragma unroll
            for (int q = 0; q < 4; q++) {
                float dx = kx[q] - jx, dy = ky[q] - jy, dz = kz[q] - jz;
                float d2 = dx * dx + dy * dy + dz * dz;
                if (kp[q] && d2 < THR_F) conflict = true;
            }
            conflict = __any_sync(0xffffffffu, conflict);
            if (!conflict && lane == (j & 31)) kp[j >> 5] = true;
        }
        #pragma unroll
        for (int q = 0; q < 4; q++) g_retain[b * Gg + lane + q * 32] = kp[q] ? 1 : 0;
    }
}

// ---------------------------------------------------------------------------
// Kernel 2: per-(group,batch) ball query + top-32 by energy + gather/normalize
// ---------------------------------------------------------------------------
__global__ __launch_bounds__(GQ_T) void group_kernel(const float4* __restrict__ pts,
                                                     const int* __restrict__ lengths,
                                                     float* __restrict__ out) {
    const int g = blockIdx.x, b = blockIdx.y;
    const float4* __restrict__ p4 = pts + (size_t)b * Nn;
    const float* __restrict__ pf = (const float*)p4;
    const int t = threadIdx.x;
    const int len = lengths[b];

    const float cx = g_centers[((size_t)b * Gg + g) * 3 + 0];
    const float cy = g_centers[((size_t)b * Gg + g) * 3 + 1];
    const float cz = g_centers[((size_t)b * Gg + g) * 3 + 2];
    const int retain = g_retain[b * Gg + g];

    __shared__ int s_cand[UK];
    __shared__ float s_e[UK];
    __shared__ int s_cnt[GQ_T];
    __shared__ int s_total;
    __shared__ int s_tidx[GS];

    // Scan contiguous chunk -> ascending global index order after prefix sum
    const int start = t * CHUNK;
    int cnt = 0;
    int cache[16];
    if (retain) {
        #pragma unroll 4
        for (int k = 0; k < CHUNK; k++) {
            const int i = start + k;
            float4 v = p4[i];
            float dx = v.x - cx, dy = v.y - cy, dz = v.z - cz;
            float d2 = dx * dx + dy * dy + dz * dz;
            if (i < len && d2 <= R2_F) {
                if (cnt < 16) cache[cnt] = i;
                cnt++;
            }
        }
    }

    // Inclusive prefix sum (Hillis-Steele) over 256 counts
    s_cnt[t] = cnt;
    __syncthreads();
    #pragma unroll
    for (int off = 1; off < GQ_T; off <<= 1) {
        int v = (t >= off) ? s_cnt[t - off] : 0;
        __syncthreads();
        s_cnt[t] += v;
        __syncthreads();
    }
    const int incl = s_cnt[t];
    const int excl = incl - cnt;
    if (t == GQ_T - 1) s_total = incl;

    if (cnt > 0 && excl < UK) {
        if (cnt <= 16) {
            for (int m = 0; m < cnt; m++) {
                int pos = excl + m;
                if (pos < UK) s_cand[pos] = cache[m];
            }
        } else {
            // rare fallback: rescan this thread's chunk
            int m = 0;
            for (int k = 0; k < CHUNK; k++) {
                const int i = start + k;
                float4 v = p4[i];
                float dx = v.x - cx, dy = v.y - cy, dz = v.z - cz;
                float d2 = dx * dx + dy * dy + dz * dz;
                if (i < len && d2 <= R2_F) {
                    int pos = excl + m;
                    if (pos < UK) s_cand[pos] = i;
                    m++;
                }
            }
        }
    }
    __syncthreads();

    const int total = s_total;
    const int numEff = total < UK ? total : UK;

    // Energies for candidate slots (pad -inf)
    if (t < UK) s_e[t] = (t < numEff) ? pf[(size_t)s_cand[t] * 4 + 3] : NEG_INF();
    __syncthreads();

    // Stable top-32 (descending value, min position on tie) — warp 0
    if (t < 32) {
        float v[4];
        bool used[4];
        #pragma unroll
        for (int q = 0; q < 4; q++) { v[q] = s_e[t + q * 32]; used[q] = false; }
        for (int r = 0; r < GS; r++) {
            float bv = NEG_INF();
            int bp = 0x7fffffff;
            #pragma unroll
            for (int q = 0; q < 4; q++) {
                const int pos = t + q * 32;
                if (!used[q] && (v[q] > bv || (v[q] == bv && pos < bp))) { bv = v[q]; bp = pos; }
            }
            argmax_red(bv, bp);
            bv = __shfl_sync(0xffffffffu, bv, 0);
            bp = __shfl_sync(0xffffffffu, bp, 0);
            if (t == (bp & 31)) used[bp >> 5] = true;
            if (t == 0) s_tidx[r] = (bv == NEG_INF()) ? -1 : s_cand[bp];
        }
    }
    __syncthreads();

    // Gather + normalize output: thread t handles element (r = t/4, c = t%4)
    if (t < GS * Cc) {
        const int r = t >> 2, c = t & 3;
        const int ti = s_tidx[r];
        const int fi = (ti == -1) ? s_tidx[0] : ti;
        float val = (fi == -1) ? 0.0f : pf[(size_t)fi * 4 + c];
        if (c < 3) {
            const float cc = (c == 0) ? cx : (c == 1) ? cy : cz;
            val -= cc;
        }
        val = __fdiv_rn(val, RADIUS_F);
        out[OUT_GROUPS + ((((size_t)b * Gg + g) * GS) + r) * Cc + c] = val;
    }
    if (t == 0 && total >= GS) atomicAdd(&g_glen[b], 1);
}

// ---------------------------------------------------------------------------
// Kernel 3: embedding mask
// ---------------------------------------------------------------------------
__global__ void mask_kernel(float* __restrict__ out) {
    const int i = blockIdx.x * blockDim.x + threadIdx.x;
    if (i < Bn * Gg) {
        const int b = i >> 7, g = i & (Gg - 1);
        out[OUT_MASK + i] = (g < g_glen[b]) ? 1.0f : 0.0f;
    }
}

extern "C" void kernel_launch(void* const* d_in, const int* in_sizes, int n_in,
                              void* d_out, int out_size) {
    const float4* pts = (const float4*)d_in[0];
    const int* lengths = (const int*)d_in[1];
    float* out = (float*)d_out;
    (void)in_sizes; (void)n_in; (void)out_size;

    fps_kernel<<<Bn, FPS_T>>>(pts, lengths, out);
    group_kernel<<<dim3(Gg, Bn), GQ_T>>>(pts, lengths, out);
    mask_kernel<<<(Bn * Gg + 255) / 256, 256>>>(out);
}

// round 2
// speedup vs baseline: 1.2529x; 1.2529x over previous
#include <cuda_runtime.h>
#include <cuda_bf16.h>
#include <cstdint>

// Problem constants
#define Bn 8
#define Nn 16384
#define Cc 4
#define Gg 128          // NUM_GROUPS
#define GS 32           // GROUP_SIZE
#define UK 128          // UPSCALE_K
#define FPS_T 1024
#define NPAIR 8            // 16 pts/thread as 8 f32x2 pairs
#define GQ_T 256
#define CHUNK (Nn / GQ_T)  // 64 points per thread

typedef unsigned long long u64t;

__device__ __forceinline__ float NEG_INF() { return __int_as_float(0xff800000); }
__device__ __forceinline__ float POS_INF() { return __int_as_float(0x7f800000); }
#define RADIUS_F 0.1f
#define R2_F 0.01f                  // f32(0.01)
#define THR_F 0.0036f               // f32((2*0.1*0.3)^2)

// Output layout: groups | centers | mask
#define OUT_GROUPS 0
#define OUT_CENTERS (Bn * Gg * GS * Cc)          // 131072
#define OUT_MASK (OUT_CENTERS + Bn * Gg * 3)     // 134144

__device__ float g_centers[Bn * Gg * 3];
__device__ int   g_retain[Bn * Gg];
__device__ int   g_glen[Bn];

// ---- f32x2 packed helpers (sm_100+) ----
__device__ __forceinline__ u64t pk2(float lo, float hi) {
    u64t r; asm("mov.b64 %0, {%1, %2};" : "=l"(r) : "f"(lo), "f"(hi)); return r;
}
__device__ __forceinline__ float plo(u64t v) { return __uint_as_float((unsigned)v); }
__device__ __forceinline__ float phi(u64t v) { return __uint_as_float((unsigned)(v >> 32)); }
__device__ __forceinline__ u64t add2(u64t a, u64t b) {
    u64t r; asm("add.rn.f32x2 %0, %1, %2;" : "=l"(r) : "l"(a), "l"(b)); return r;
}
__device__ __forceinline__ u64t mul2(u64t a, u64t b) {
    u64t r; asm("mul.rn.f32x2 %0, %1, %2;" : "=l"(r) : "l"(a), "l"(b)); return r;
}
__device__ __forceinline__ u64t fma2(u64t a, u64t b, u64t c) {
    u64t r; asm("fma.rn.f32x2 %0, %1, %2, %3;" : "=l"(r) : "l"(a), "l"(b), "l"(c)); return r;
}

// ---------------------------------------------------------------------------
// Kernel 1: FPS (one block per batch) + fused cluster-NMS + centers output
// ---------------------------------------------------------------------------
__global__ __launch_bounds__(FPS_T) void fps_kernel(const float4* __restrict__ pts,
                                                    const int* __restrict__ lengths,
                                                    float* __restrict__ out) {
    const int b = blockIdx.x;
    const float4* __restrict__ p = pts + (size_t)b * Nn;
    const int len = lengths[b];
    const int t = threadIdx.x;
    const int lane = t & 31;

    __shared__ float s_c[3];
    __shared__ float s_centers[Gg * 3];
    __shared__ u64t  s_key[2];

    if (t == 0) {
        g_glen[b] = 0;
        s_key[0] = 0ull; s_key[1] = 0ull;
        float4 v = p[0];
        s_c[0] = v.x; s_c[1] = v.y; s_c[2] = v.z;
        s_centers[0] = v.x; s_centers[1] = v.y; s_centers[2] = v.z;
    }

    // Load 16 points/thread as 8 packed pairs: pair j = (t + 2j*1024, t + (2j+1)*1024)
    u64t Xp[NPAIR], Yp[NPAIR], Zp[NPAIR];
    float Mlo[NPAIR], Mhi[NPAIR];
    #pragma unroll
    for (int j = 0; j < NPAIR; j++) {
        const int i0 = t + (2 * j) * FPS_T;
        const int i1 = i0 + FPS_T;
        float4 a = p[i0];
        float4 c = p[i1];
        Xp[j] = pk2(a.x, c.x);
        Yp[j] = pk2(a.y, c.y);
        Zp[j] = pk2(a.z, c.z);
        Mlo[j] = (i0 < len) ? POS_INF() : NEG_INF();
        Mhi[j] = (i1 < len) ? POS_INF() : NEG_INF();
    }
    __syncthreads();

    for (int s = 1; s < Gg; s++) {
        const int q = s & 1;
        const float cx = s_c[0], cy = s_c[1], cz = s_c[2];
        const u64t ncx = pk2(-cx, -cx);
        const u64t ncy = pk2(-cy, -cy);
        const u64t ncz = pk2(-cz, -cz);

        #pragma unroll
        for (int j = 0; j < NPAIR; j++) {
            u64t dx = add2(Xp[j], ncx);
            u64t dy = add2(Yp[j], ncy);
            u64t dz = add2(Zp[j], ncz);
            u64t d = mul2(dx, dx);
            d = fma2(dy, dy, d);
            d = fma2(dz, dz, d);
            Mlo[j] = fminf(Mlo[j], plo(d));
            Mhi[j] = fminf(Mhi[j], phi(d));
        }

        // value-only max over this thread's 16 mins (log tree)
        float bv = NEG_INF();
        #pragma unroll
        for (int j = 0; j < NPAIR; j++) bv = fmaxf(bv, fmaxf(Mlo[j], Mhi[j]));

        // warp max on bits (distances >= 0 so s32 order == float order; -inf < 0 ok)
        const int bb = __float_as_int(bv);
        const int wmax = __reduce_max_sync(0xffffffffu, bb);

        unsigned gi = 0xffffffffu;
        if (bb == wmax) {
            // smallest local k whose mind equals bv (exact bit equality)
            int bk = 0x7fffffff;
            #pragma unroll
            for (int j = NPAIR - 1; j >= 0; j--) {
                if (Mhi[j] == bv) bk = 2 * j + 1;
                if (Mlo[j] == bv) bk = 2 * j;
            }
            gi = ((unsigned)bk << 10) + (unsigned)t;   // global index = k*1024 + t
        }
        const unsigned gmin = __reduce_min_sync(0xffffffffu, gi);
        if (lane == 0) {
            u64t key = ((u64t)(unsigned)wmax << 32) | (u64t)(0xffffffffu - gmin);
            atomicMax(&s_key[q], key);
        }
        if (t == 0) s_key[q ^ 1] = 0ull;   // reset slot for iteration s+1
        __syncthreads();

        const u64t kk = s_key[q];
        const unsigned g = 0xffffffffu - (unsigned)kk;
        if (t == (int)(g & 1023u)) {       // owner broadcasts next center from regs
            const int k = (int)(g >> 10);
            const int j = k >> 1;
            const float nx = (k & 1) ? phi(Xp[j]) : plo(Xp[j]);
            const float ny = (k & 1) ? phi(Yp[j]) : plo(Yp[j]);
            const float nz = (k & 1) ? phi(Zp[j]) : plo(Zp[j]);
            s_c[0] = nx; s_c[1] = ny; s_c[2] = nz;
            s_centers[s * 3 + 0] = nx;
            s_centers[s * 3 + 1] = ny;
            s_centers[s * 3 + 2] = nz;
        }
        __syncthreads();
    }

    // Write centers
    for (int i = t; i < Gg * 3; i += FPS_T) {
        float v = s_centers[i];
        g_centers[(size_t)b * Gg * 3 + i] = v;
        out[OUT_CENTERS + (size_t)b * Gg * 3 + i] = v;
    }

    // Greedy cluster-NMS in FPS order (warp 0)
    if (t < 32) {
        float kx[4], ky[4], kz[4];
        bool kp[4];
        #pragma unroll
        for (int q = 0; q < 4; q++) {
            const int i = lane + q * 32;
            kx[q] = s_centers[i * 3 + 0];
            ky[q] = s_centers[i * 3 + 1];
            kz[q] = s_centers[i * 3 + 2];
            kp[q] = false;
        }
        for (int j = 0; j < Gg; j++) {
            const float jx = s_centers[j * 3 + 0];
            const float jy = s_centers[j * 3 + 1];
            const float jz = s_centers[j * 3 + 2];
            bool conflict = false;
            #pragma unroll
            for (int q = 0; q < 4; q++) {
                float dx = kx[q] - jx, dy = ky[q] - jy, dz = kz[q] - jz;
                float d2 = dx * dx + dy * dy + dz * dz;
                if (kp[q] && d2 < THR_F) conflict = true;
            }
            conflict = __any_sync(0xffffffffu, conflict);
            if (!conflict && lane == (j & 31)) kp[j >> 5] = true;
        }
        #pragma unroll
        for (int q = 0; q < 4; q++) g_retain[b * Gg + lane + q * 32] = kp[q] ? 1 : 0;
    }
}

// ---------------------------------------------------------------------------
// Kernel 2: per-(group,batch) ball query + top-32 by energy + gather/normalize
// ---------------------------------------------------------------------------
__global__ __launch_bounds__(GQ_T) void group_kernel(const float4* __restrict__ pts,
                                                     const int* __restrict__ lengths,
                                                     float* __restrict__ out) {
    const int g = blockIdx.x, b = blockIdx.y;
    const float4* __restrict__ p4 = pts + (size_t)b * Nn;
    const float* __restrict__ pf = (const float*)p4;
    const int t = threadIdx.x;
    const int lane = t & 31, warp = t >> 5;
    const int len = lengths[b];

    const float cx = g_centers[((size_t)b * Gg + g) * 3 + 0];
    const float cy = g_centers[((size_t)b * Gg + g) * 3 + 1];
    const float cz = g_centers[((size_t)b * Gg + g) * 3 + 2];
    const int retain = g_retain[b * Gg + g];

    __shared__ int s_cand[UK];
    __shared__ int s_w[8];
    __shared__ int s_tidx[GS];

    // Scan contiguous chunk (ascending index order preserved via prefix sum)
    const int start = t * CHUNK;
    const int lim0 = len - start;                 // local k valid iff k < lim0
    int cnt = 0;
    int cache[16];
    if (retain) {
        const u64t ncx = pk2(-cx, -cx);
        const u64t ncy = pk2(-cy, -cy);
        const u64t ncz = pk2(-cz, -cz);
        #pragma unroll 4
        for (int u = 0; u < CHUNK / 2; u++) {
            const int i0 = start + 2 * u;
            float4 a = p4[i0];
            float4 c = p4[i0 + 1];
            u64t xx = pk2(a.x, c.x), yy = pk2(a.y, c.y), zz = pk2(a.z, c.z);
            u64t dx = add2(xx, ncx), dy = add2(yy, ncy), dz = add2(zz, ncz);
            u64t d = mul2(dx, dx);
            d = fma2(dy, dy, d);
            d = fma2(dz, dz, d);
            if ((2 * u < lim0) && (plo(d) <= R2_F)) { if (cnt < 16) cache[cnt] = i0; cnt++; }
            if ((2 * u + 1 < lim0) && (phi(d) <= R2_F)) { if (cnt < 16) cache[cnt] = i0 + 1; cnt++; }
        }
    }

    // block prefix sum: warp shfl scan + cross-warp scan (2 barriers)
    int v = cnt;
    #pragma unroll
    for (int off = 1; off < 32; off <<= 1) {
        int o = __shfl_up_sync(0xffffffffu, v, off);
        if (lane >= off) v += o;
    }
    if (lane == 31) s_w[warp] = v;
    __syncthreads();
    if (t < 8) {
        int w = s_w[t];
        #pragma unroll
        for (int off = 1; off < 8; off <<= 1) {
            int o = __shfl_up_sync(0x000000ffu, w, off);
            if (t >= off) w += o;
        }
        s_w[t] = w;
    }
    __syncthreads();
    const int woff = (warp == 0) ? 0 : s_w[warp - 1];
    const int incl = woff + v;
    const int excl = incl - cnt;
    const int total = s_w[7];

    if (cnt > 0 && excl < UK) {
        if (cnt <= 16) {
            for (int m = 0; m < cnt; m++) {
                int pos = excl + m;
                if (pos < UK) s_cand[pos] = cache[m];
            }
        } else {
            int m = 0;
            for (int k = 0; k < CHUNK; k++) {
                const int i = start + k;
                float4 vv = p4[i];
                float dx = vv.x - cx, dy = vv.y - cy, dz = vv.z - cz;
                float d2 = dx * dx + dy * dy + dz * dz;
                if (k < lim0 && d2 <= R2_F) {
                    int pos = excl + m;
                    if (pos < UK) s_cand[pos] = i;
                    m++;
                }
            }
        }
    }
    __syncthreads();

    const int numEff = total < UK ? total : UK;

    // Stable top-32: warp-bitonic full sort of 128 u64 keys (value || pos-complement)
    if (t < 32) {
        u64t key[4];
        #pragma unroll
        for (int r = 0; r < 4; r++) {
            const int slot = r * 32 + t;
            unsigned vb = 0u;
            if (slot < numEff) {
                unsigned eb = __float_as_uint(pf[(size_t)s_cand[slot] * 4 + 3]);
                vb = (eb & 0x80000000u) ? ~eb : (eb | 0x80000000u);
            }
            key[r] = ((u64t)vb << 32) | (u64t)(127 - slot);
        }
        #pragma unroll
        for (int k = 2; k <= 128; k <<= 1) {
            #pragma unroll
            for (int j = k >> 1; j > 0; j >>= 1) {
                if (j >= 32) {
                    const int rj = j >> 5;
                    #pragma unroll
                    for (int r = 0; r < 4; r++) {
                        const int pr = r ^ rj;
                        if (pr > r) {
                            const int e = r * 32 + t;
                            const bool dsc = ((e & k) == 0);
                            u64t a = key[r], c = key[pr];
                            u64t mx = a > c ? a : c;
                            u64t mn = a > c ? c : a;
                            key[r] = dsc ? mx : mn;
                            key[pr] = dsc ? mn : mx;
                        }
                    }
                } else {
                    #pragma unroll
                    for (int r = 0; r < 4; r++) {
                        const int e = r * 32 + t;
                        u64t o = __shfl_xor_sync(0xffffffffu, key[r], j);
                        const bool low = ((t & j) == 0);
                        const bool dsc = ((e & k) == 0);
                        const bool takeMax = (dsc == low);
                        u64t mx = key[r] > o ? key[r] : o;
                        u64t mn = key[r] > o ? o : key[r];
                        key[r] = takeMax ? mx : mn;
                    }
                }
            }
        }
        // rank t = element t = key[0]
        const u64t k0 = key[0];
        const int slot = 127 - (int)(k0 & 127ull);
        s_tidx[t] = ((unsigned)(k0 >> 32) >= 0x80000000u) ? s_cand[slot] : -1;
    }
    __syncthreads();

    // Gather + normalize: thread t -> (row r = t/4, col c = t%4)
    if (t < GS * Cc) {
        const int r = t >> 2, c = t & 3;
        const int ti = s_tidx[r];
        const int fi = (ti == -1) ? s_tidx[0] : ti;
        float val = (fi == -1) ? 0.0f : pf[(size_t)fi * 4 + c];
        if (c < 3) {
            const float cc = (c == 0) ? cx : (c == 1) ? cy : cz;
            val -= cc;
        }
        val = __fdiv_rn(val, RADIUS_F);
        out[OUT_GROUPS + ((((size_t)b * Gg + g) * GS) + r) * Cc + c] = val;
    }
    if (t == 0 && total >= GS) atomicAdd(&g_glen[b], 1);
}

// ---------------------------------------------------------------------------
// Kernel 3: embedding mask
// ---------------------------------------------------------------------------
__global__ void mask_kernel(float* __restrict__ out) {
    const int i = blockIdx.x * blockDim.x + threadIdx.x;
    if (i < Bn * Gg) {
        const int b = i >> 7, g = i & (Gg - 1);
        out[OUT_MASK + i] = (g < g_glen[b]) ? 1.0f : 0.0f;
    }
}

extern "C" void kernel_launch(void* const* d_in, const int* in_sizes, int n_in,
                              void* d_out, int out_size) {
    const float4* pts = (const float4*)d_in[0];
    const int* lengths = (const int*)d_in[1];
    float* out = (float*)d_out;
    (void)in_sizes; (void)n_in; (void)out_size;

    fps_kernel<<<Bn, FPS_T>>>(pts, lengths, out);
    group_kernel<<<dim3(Gg, Bn), GQ_T>>>(pts, lengths, out);
    mask_kernel<<<(Bn * Gg + 255) / 256, 256>>>(out);
}

// round 3
// speedup vs baseline: 1.3255x; 1.0580x over previous
#include <cuda_runtime.h>
#include <cuda_bf16.h>
#include <cstdint>

// Problem constants
#define Bn 8
#define Nn 16384
#define Cc 4
#define Gg 128          // NUM_GROUPS
#define GS 32           // GROUP_SIZE
#define UK 128          // UPSCALE_K
#define CLU 4           // cluster size for FPS
#define FT 1024         // FPS threads per CTA
#define PPC (Nn / CLU)  // 4096 points per CTA
#define FPAIR 2         // PPC / FT / 2 packed pairs per thread
#define GQ_T 256
#define CHUNK (Nn / GQ_T)  // 64 points per thread

typedef unsigned long long u64t;

__device__ __forceinline__ float NEG_INF() { return __int_as_float(0xff800000); }
__device__ __forceinline__ float POS_INF() { return __int_as_float(0x7f800000); }
#define RADIUS_F 0.1f
#define R2_F 0.01f                  // f32(0.01)
#define THR_F 0.0036f               // f32((2*0.1*0.3)^2)

// Output layout: groups | centers | mask
#define OUT_GROUPS 0
#define OUT_CENTERS (Bn * Gg * GS * Cc)          // 131072
#define OUT_MASK (OUT_CENTERS + Bn * Gg * 3)     // 134144

__device__ float g_centers[Bn * Gg * 3];
__device__ int   g_retain[Bn * Gg];
__device__ int   g_glen[Bn];

// ---- f32x2 packed helpers (sm_100+) ----
__device__ __forceinline__ u64t pk2(float lo, float hi) {
    u64t r; asm("mov.b64 %0, {%1, %2};" : "=l"(r) : "f"(lo), "f"(hi)); return r;
}
__device__ __forceinline__ float plo(u64t v) { return __uint_as_float((unsigned)v); }
__device__ __forceinline__ float phi(u64t v) { return __uint_as_float((unsigned)(v >> 32)); }
__device__ __forceinline__ u64t add2(u64t a, u64t b) {
    u64t r; asm("add.rn.f32x2 %0, %1, %2;" : "=l"(r) : "l"(a), "l"(b)); return r;
}
__device__ __forceinline__ u64t mul2(u64t a, u64t b) {
    u64t r; asm("mul.rn.f32x2 %0, %1, %2;" : "=l"(r) : "l"(a), "l"(b)); return r;
}
__device__ __forceinline__ u64t fma2(u64t a, u64t b, u64t c) {
    u64t r; asm("fma.rn.f32x2 %0, %1, %2, %3;" : "=l"(r) : "l"(a), "l"(b), "l"(c)); return r;
}

// ---- cluster helpers ----
__device__ __forceinline__ uint32_t smem_u32(const void* p) {
    uint32_t a;
    asm("{ .reg .u64 t; cvta.to.shared.u64 t, %1; cvt.u32.u64 %0, t; }" : "=r"(a) : "l"(p));
    return a;
}
__device__ __forceinline__ void st_clu_u64(uint32_t laddr, uint32_t rank, u64t v) {
    uint32_t ra;
    asm("mapa.shared::cluster.u32 %0, %1, %2;" : "=r"(ra) : "r"(laddr), "r"(rank));
    asm volatile("st.shared::cluster.u64 [%0], %1;" :: "r"(ra), "l"(v) : "memory");
}
__device__ __forceinline__ void st_clu_f32(uint32_t laddr, uint32_t rank, float v) {
    uint32_t ra;
    asm("mapa.shared::cluster.u32 %0, %1, %2;" : "=r"(ra) : "r"(laddr), "r"(rank));
    asm volatile("st.shared::cluster.f32 [%0], %1;" :: "r"(ra), "f"(v) : "memory");
}
__device__ __forceinline__ void cluster_sync_() {
    asm volatile("barrier.cluster.arrive.aligned;" ::: "memory");
    asm volatile("barrier.cluster.wait.aligned;" ::: "memory");
}

// ---------------------------------------------------------------------------
// Kernel 1: cluster-parallel FPS (4 CTAs per batch) + NMS + centers output
// ---------------------------------------------------------------------------
__global__ __launch_bounds__(FT) __cluster_dims__(CLU, 1, 1)
void fps_kernel(const float4* __restrict__ pts,
                const int* __restrict__ lengths,
                float* __restrict__ out) {
    const int bid = blockIdx.x;
    const int b = bid / CLU;
    const int r = bid % CLU;              // cluster rank
    const float4* __restrict__ p = pts + (size_t)b * Nn;
    const int len = lengths[b];
    const int t = threadIdx.x;
    const int lane = t & 31, warp = t >> 5;
    const int base = r * PPC;

    struct __align__(16) Entry { u64t key; float x, y; };
    __shared__ Entry s_e[32];
    __shared__ float s_ez[32];
    __shared__ u64t  s_ak[2][CLU];
    __shared__ u64t  s_axy[2][CLU];
    __shared__ float s_az[2][CLU];
    __shared__ float s_centers[Gg * 3];

    // Load 4096 pts/CTA: pair j covers local idx (t + 2j*1024, t + (2j+1)*1024)
    u64t Xp[FPAIR], Yp[FPAIR], Zp[FPAIR];
    float Mlo[FPAIR], Mhi[FPAIR];
    #pragma unroll
    for (int j = 0; j < FPAIR; j++) {
        const int i0 = base + t + (2 * j) * FT;
        const int i1 = i0 + FT;
        float4 a = __ldg(p + i0);
        float4 c = __ldg(p + i1);
        Xp[j] = pk2(a.x, c.x);
        Yp[j] = pk2(a.y, c.y);
        Zp[j] = pk2(a.z, c.z);
        Mlo[j] = (i0 < len) ? POS_INF() : NEG_INF();
        Mhi[j] = (i1 < len) ? POS_INF() : NEG_INF();
    }

    // initial center = point 0 (loaded by every thread; converged)
    float4 c0 = __ldg(p);
    float cx = c0.x, cy = c0.y, cz = c0.z;
    if (r == 0 && t == 0) {
        g_glen[b] = 0;
        s_centers[0] = cx; s_centers[1] = cy; s_centers[2] = cz;
    }

    const uint32_t a_ak  = smem_u32(&s_ak[0][0]);
    const uint32_t a_axy = smem_u32(&s_axy[0][0]);
    const uint32_t a_az  = smem_u32(&s_az[0][0]);

    for (int s = 1; s < Gg; s++) {
        const int q = s & 1;
        const u64t ncx = pk2(-cx, -cx);
        const u64t ncy = pk2(-cy, -cy);
        const u64t ncz = pk2(-cz, -cz);

        #pragma unroll
        for (int j = 0; j < FPAIR; j++) {
            u64t dx = add2(Xp[j], ncx);
            u64t dy = add2(Yp[j], ncy);
            u64t dz = add2(Zp[j], ncz);
            u64t d = mul2(dx, dx);
            d = fma2(dy, dy, d);
            d = fma2(dz, dz, d);
            Mlo[j] = fminf(Mlo[j], plo(d));
            Mhi[j] = fminf(Mhi[j], phi(d));
        }

        // thread-local max (value only)
        float bv = fmaxf(fmaxf(Mlo[0], Mhi[0]), fmaxf(Mlo[1], Mhi[1]));

        // warp max on bits (s32 order ok: values >= 0 or -inf)
        const int bb = __float_as_int(bv);
        const int wmax = __reduce_max_sync(0xffffffffu, bb);

        // min local slot k matching bv (descending priority => min local index)
        int bk = 3;
        if (Mlo[1] == bv) bk = 2;
        if (Mhi[0] == bv) bk = 1;
        if (Mlo[0] == bv) bk = 0;

        unsigned gl = (bb == wmax) ? ((unsigned)(bk << 10) + (unsigned)t) : 0xffffffffu;
        const unsigned gmin = __reduce_min_sync(0xffffffffu, gl);

        // orderable unsigned of wmax (handles -inf for all-invalid ranges)
        const unsigned tv = (wmax >= 0) ? ((unsigned)wmax | 0x80000000u) : ~(unsigned)wmax;
        const u64t wkey = ((u64t)tv << 32) | (u64t)(0xffffffffu - (unsigned)(base + (int)gmin));

        // candidate coords for my own bk; then pull from winner lane
        const int jj = bk >> 1;
        const bool hi = bk & 1;
        float sx = hi ? phi(Xp[jj]) : plo(Xp[jj]);
        float sy = hi ? phi(Yp[jj]) : plo(Yp[jj]);
        float sz = hi ? phi(Zp[jj]) : plo(Zp[jj]);
        const int src = (int)(gmin & 31u);
        sx = __shfl_sync(0xffffffffu, sx, src);
        sy = __shfl_sync(0xffffffffu, sy, src);
        sz = __shfl_sync(0xffffffffu, sz, src);

        if (lane == 0) {
            s_e[warp].key = wkey; s_e[warp].x = sx; s_e[warp].y = sy;
            s_ez[warp] = sz;
        }
        __syncthreads();

        if (warp == 0) {
            u64t k = s_e[lane].key;
            float x = s_e[lane].x, y = s_e[lane].y, z = s_ez[lane];
            u64t m = k;
            #pragma unroll
            for (int off = 16; off > 0; off >>= 1) {
                u64t o = __shfl_xor_sync(0xffffffffu, m, off);
                m = (o > m) ? o : m;
            }
            const unsigned ball = __ballot_sync(0xffffffffu, k == m);
            const int srcw = __ffs(ball) - 1;
            x = __shfl_sync(0xffffffffu, x, srcw);
            y = __shfl_sync(0xffffffffu, y, srcw);
            z = __shfl_sync(0xffffffffu, z, srcw);
            if (lane < CLU) {
                const uint32_t slot = (uint32_t)(q * CLU + r);
                st_clu_u64(a_ak + slot * 8, (uint32_t)lane, m);
                st_clu_u64(a_axy + slot * 8, (uint32_t)lane, pk2(x, y));
                st_clu_f32(a_az + slot * 4, (uint32_t)lane, z);
            }
        }
        cluster_sync_();

        // pick winner among CLU ranks (local reads)
        u64t km = s_ak[q][0];
        int w = 0;
        #pragma unroll
        for (int i = 1; i < CLU; i++) {
            u64t ki = s_ak[q][i];
            if (ki > km) { km = ki; w = i; }
        }
        const u64t xy = s_axy[q][w];
        cx = plo(xy); cy = phi(xy); cz = s_az[q][w];
        if (r == 0 && t == 0) {
            s_centers[s * 3 + 0] = cx;
            s_centers[s * 3 + 1] = cy;
            s_centers[s * 3 + 2] = cz;
        }
    }

    if (r != 0) return;
    __syncthreads();

    // Write centers
    for (int i = t; i < Gg * 3; i += FT) {
        float v = s_centers[i];
        g_centers[(size_t)b * Gg * 3 + i] = v;
        out[OUT_CENTERS + (size_t)b * Gg * 3 + i] = v;
    }

    // Greedy cluster-NMS in FPS order (warp 0)
    if (t < 32) {
        float kx[4], ky[4], kz[4];
        bool kp[4];
        #pragma unroll
        for (int qq = 0; qq < 4; qq++) {
            const int i = lane + qq * 32;
            kx[qq] = s_centers[i * 3 + 0];
            ky[qq] = s_centers[i * 3 + 1];
            kz[qq] = s_centers[i * 3 + 2];
            kp[qq] = false;
        }
        for (int j = 0; j < Gg; j++) {
            const float jx = s_centers[j * 3 + 0];
            const float jy = s_centers[j * 3 + 1];
            const float jz = s_centers[j * 3 + 2];
            bool conflict = false;
            #pragma unroll
            for (int qq = 0; qq < 4; qq++) {
                float dx = kx[qq] - jx, dy = ky[qq] - jy, dz = kz[qq] - jz;
                float d2 = dx * dx + dy * dy + dz * dz;
                if (kp[qq] && d2 < THR_F) conflict = true;
            }
            conflict = __any_sync(0xffffffffu, conflict);
            if (!conflict && lane == (j & 31)) kp[j >> 5] = true;
        }
        #pragma unroll
        for (int qq = 0; qq < 4; qq++) g_retain[b * Gg + lane + qq * 32] = kp[qq] ? 1 : 0;
    }
}

// ---------------------------------------------------------------------------
// Kernel 2: per-(group,batch) ball query + top-32 by energy + gather/normalize
// ---------------------------------------------------------------------------
__global__ __launch_bounds__(GQ_T) void group_kernel(const float4* __restrict__ pts,
                                                     const int* __restrict__ lengths,
                                                     float* __restrict__ out) {
    const int g = blockIdx.x, b = blockIdx.y;
    const float4* __restrict__ p4 = pts + (size_t)b * Nn;
    const float* __restrict__ pf = (const float*)p4;
    const int t = threadIdx.x;
    const int lane = t & 31, warp = t >> 5;
    const int len = lengths[b];

    const float cx = g_centers[((size_t)b * Gg + g) * 3 + 0];
    const float cy = g_centers[((size_t)b * Gg + g) * 3 + 1];
    const float cz = g_centers[((size_t)b * Gg + g) * 3 + 2];
    const int retain = g_retain[b * Gg + g];

    __shared__ int s_cand[UK];
    __shared__ int s_w[8];
    __shared__ int s_tidx[GS];

    const int start = t * CHUNK;
    const int lim0 = len - start;
    int cnt = 0;
    int cache[16];
    if (retain) {
        const u64t ncx = pk2(-cx, -cx);
        const u64t ncy = pk2(-cy, -cy);
        const u64t ncz = pk2(-cz, -cz);
        #pragma unroll 4
        for (int u = 0; u < CHUNK / 2; u++) {
            const int i0 = start + 2 * u;
            float4 a = p4[i0];
            float4 c = p4[i0 + 1];
            u64t xx = pk2(a.x, c.x), yy = pk2(a.y, c.y), zz = pk2(a.z, c.z);
            u64t dx = add2(xx, ncx), dy = add2(yy, ncy), dz = add2(zz, ncz);
            u64t d = mul2(dx, dx);
            d = fma2(dy, dy, d);
            d = fma2(dz, dz, d);
            if ((2 * u < lim0) && (plo(d) <= R2_F)) { if (cnt < 16) cache[cnt] = i0; cnt++; }
            if ((2 * u + 1 < lim0) && (phi(d) <= R2_F)) { if (cnt < 16) cache[cnt] = i0 + 1; cnt++; }
        }
    }

    // block prefix sum: warp shfl scan + cross-warp scan
    int v = cnt;
    #pragma unroll
    for (int off = 1; off < 32; off <<= 1) {
        int o = __shfl_up_sync(0xffffffffu, v, off);
        if (lane >= off) v += o;
    }
    if (lane == 31) s_w[warp] = v;
    __syncthreads();
    if (t < 8) {
        int w = s_w[t];
        #pragma unroll
        for (int off = 1; off < 8; off <<= 1) {
            int o = __shfl_up_sync(0x000000ffu, w, off);
            if (t >= off) w += o;
        }
        s_w[t] = w;
    }
    __syncthreads();
    const int woff = (warp == 0) ? 0 : s_w[warp - 1];
    const int incl = woff + v;
    const int excl = incl - cnt;
    const int total = s_w[7];

    if (cnt > 0 && excl < UK) {
        if (cnt <= 16) {
            for (int m = 0; m < cnt; m++) {
                int pos = excl + m;
                if (pos < UK) s_cand[pos] = cache[m];
            }
        } else {
            int m = 0;
            for (int k = 0; k < CHUNK; k++) {
                const int i = start + k;
                float4 vv = p4[i];
                float dx = vv.x - cx, dy = vv.y - cy, dz = vv.z - cz;
                float d2 = dx * dx + dy * dy + dz * dz;
                if (k < lim0 && d2 <= R2_F) {
                    int pos = excl + m;
                    if (pos < UK) s_cand[pos] = i;
                    m++;
                }
            }
        }
    }
    __syncthreads();

    const int numEff = total < UK ? total : UK;

    // Stable top-32: warp-bitonic full sort of 128 u64 keys (value || pos-complement)
    if (t < 32) {
        u64t key[4];
        #pragma unroll
        for (int rr = 0; rr < 4; rr++) {
            const int slot = rr * 32 + t;
            unsigned vb = 0u;
            if (slot < numEff) {
                unsigned eb = __float_as_uint(pf[(size_t)s_cand[slot] * 4 + 3]);
                vb = (eb & 0x80000000u) ? ~eb : (eb | 0x80000000u);
            }
            key[rr] = ((u64t)vb << 32) | (u64t)(127 - slot);
        }
        #pragma unroll
        for (int k = 2; k <= 128; k <<= 1) {
            #pragma unroll
            for (int j = k >> 1; j > 0; j >>= 1) {
                if (j >= 32) {
                    const int rj = j >> 5;
                    #pragma unroll
                    for (int rr = 0; rr < 4; rr++) {
                        const int pr = rr ^ rj;
                        if (pr > rr) {
                            const int e = rr * 32 + t;
                            const bool dsc = ((e & k) == 0);
                            u64t a = key[rr], c = key[pr];
                            u64t mx = a > c ? a : c;
                            u64t mn = a > c ? c : a;
                            key[rr] = dsc ? mx : mn;
                            key[pr] = dsc ? mn : mx;
                        }
                    }
                } else {
                    #pragma unroll
                    for (int rr = 0; rr < 4; rr++) {
                        const int e = rr * 32 + t;
                        u64t o = __shfl_xor_sync(0xffffffffu, key[rr], j);
                        const bool low = ((t & j) == 0);
                        const bool dsc = ((e & k) == 0);
                        const bool takeMax = (dsc == low);
                        u64t mx = key[rr] > o ? key[rr] : o;
                        u64t mn = key[rr] > o ? o : key[rr];
                        key[rr] = takeMax ? mx : mn;
                    }
                }
            }
        }
        const u64t k0 = key[0];
        const int slot = 127 - (int)(k0 & 127ull);
        s_tidx[t] = ((unsigned)(k0 >> 32) >= 0x80000000u) ? s_cand[slot] : -1;
    }
    __syncthreads();

    if (t < GS * Cc) {
        const int rr = t >> 2, c = t & 3;
        const int ti = s_tidx[rr];
        const int fi = (ti == -1) ? s_tidx[0] : ti;
        float val = (fi == -1) ? 0.0f : pf[(size_t)fi * 4 + c];
        if (c < 3) {
            const float cc = (c == 0) ? cx : (c == 1) ? cy : cz;
            val -= cc;
        }
        val = __fdiv_rn(val, RADIUS_F);
        out[OUT_GROUPS + ((((size_t)b * Gg + g) * GS) + rr) * Cc + c] = val;
    }
    if (t == 0 && total >= GS) atomicAdd(&g_glen[b], 1);
}

// ---------------------------------------------------------------------------
// Kernel 3: embedding mask
// ---------------------------------------------------------------------------
__global__ void mask_kernel(float* __restrict__ out) {
    const int i = blockIdx.x * blockDim.x + threadIdx.x;
    if (i < Bn * Gg) {
        const int b = i >> 7, g = i & (Gg - 1);
        out[OUT_MASK + i] = (g < g_glen[b]) ? 1.0f : 0.0f;
    }
}

extern "C" void kernel_launch(void* const* d_in, const int* in_sizes, int n_in,
                              void* d_out, int out_size) {
    const float4* pts = (const float4*)d_in[0];
    const int* lengths = (const int*)d_in[1];
    float* out = (float*)d_out;
    (void)in_sizes; (void)n_in; (void)out_size;

    fps_kernel<<<Bn * CLU, FT>>>(pts, lengths, out);
    group_kernel<<<dim3(Gg, Bn), GQ_T>>>(pts, lengths, out);
    mask_kernel<<<(Bn * Gg + 255) / 256, 256>>>(out);
}